// round 2
// baseline (speedup 1.0000x reference)
#include <cuda_runtime.h>
#include <math.h>

#define BATCH 4096
#define C1O 10
#define H1 62
#define P1 31
#define FEAT 3920
#define GH 64
#define NE 8
#define HID 128
#define HID2 64
#define NOUT 1000

// ---------------- scratch (device globals; no runtime allocation) ----------------
__device__ float g_c1[(size_t)BATCH * C1O * H1 * H1];
__device__ float g_p1[(size_t)BATCH * C1O * P1 * P1];
__device__ float g_feat[(size_t)BATCH * FEAT];
__device__ float g_gh[(size_t)BATCH * GH];
__device__ float g_h1[(size_t)BATCH * 2 * HID];
__device__ float g_h2[(size_t)BATCH * 2 * HID2];
__device__ float g_gatew[BATCH * 2];
__device__ int   g_list[NE * BATCH];
__device__ int   g_cnt[NE];
__device__ double g_sum[C1O], g_sumsq[C1O];
__device__ float g_bnA[C1O], g_bnB[C1O];

// ---------------- init: zero d_out, reset counters/stats ----------------
__global__ void init_kernel(float* out) {
    size_t stride = (size_t)gridDim.x * blockDim.x;
    for (size_t i = (size_t)blockIdx.x * blockDim.x + threadIdx.x;
         i < (size_t)BATCH * NOUT; i += stride)
        out[i] = 0.f;
    if (blockIdx.x == 0 && threadIdx.x < 32) {
        if (threadIdx.x < NE) g_cnt[threadIdx.x] = 0;
        if (threadIdx.x < C1O) { g_sum[threadIdx.x] = 0.0; g_sumsq[threadIdx.x] = 0.0; }
    }
}

// ---------------- conv1 (3->10, 5x5, pad1) + per-channel stats ----------------
__global__ __launch_bounds__(256) void conv1_kernel(const float* __restrict__ x,
                                                    const float* __restrict__ w,
                                                    const float* __restrict__ b) {
    extern __shared__ float sm[];
    float* pin = sm;                // [3][66][68] = 13464
    float* ws  = sm + 3 * 66 * 68;  // 750
    float* bs  = ws + 750;          // 10
    const int n = blockIdx.x, tid = threadIdx.x;

    for (int i = tid; i < 3 * 66 * 68; i += 256) pin[i] = 0.f;
    for (int i = tid; i < 750; i += 256) ws[i] = w[i];
    if (tid < 10) bs[tid] = b[tid];
    __syncthreads();

    const float* xn = x + (size_t)n * 3 * 64 * 64;
    for (int i = tid; i < 3 * 64 * 64; i += 256) {
        int c = i >> 12, r = (i >> 6) & 63, cc = i & 63;
        pin[(c * 66 + r + 1) * 68 + cc + 1] = xn[i];
    }
    __syncthreads();

    __shared__ float rs1, rs2;
    for (int co = 0; co < 10; ++co) {
        float s1 = 0.f, s2 = 0.f;
        for (int g = tid; g < 62 * 8; g += 256) {
            int y = g >> 3, xg = (g & 7) << 3;
            float acc[8];
#pragma unroll
            for (int j = 0; j < 8; j++) acc[j] = bs[co];
#pragma unroll
            for (int ci = 0; ci < 3; ci++) {
#pragma unroll
                for (int ky = 0; ky < 5; ky++) {
                    const float* row = &pin[(ci * 66 + y + ky) * 68 + xg];
                    float rr[12];
#pragma unroll
                    for (int t = 0; t < 12; t++) rr[t] = row[t];
                    const float* wr = &ws[(co * 3 + ci) * 25 + ky * 5];
#pragma unroll
                    for (int kx = 0; kx < 5; kx++) {
                        float wv = wr[kx];
#pragma unroll
                        for (int j = 0; j < 8; j++) acc[j] = fmaf(rr[j + kx], wv, acc[j]);
                    }
                }
            }
            size_t base = (((size_t)n * 10 + co) * 62 + y) * 62;
#pragma unroll
            for (int j = 0; j < 8; j++) {
                int xx = xg + j;
                if (xx < 62) {
                    float v = acc[j];
                    g_c1[base + xx] = v;
                    s1 += v; s2 += v * v;
                }
            }
        }
#pragma unroll
        for (int off = 16; off > 0; off >>= 1) {
            s1 += __shfl_down_sync(0xffffffffu, s1, off);
            s2 += __shfl_down_sync(0xffffffffu, s2, off);
        }
        if (tid == 0) { rs1 = 0.f; rs2 = 0.f; }
        __syncthreads();
        if ((tid & 31) == 0) { atomicAdd(&rs1, s1); atomicAdd(&rs2, s2); }
        __syncthreads();
        if (tid == 0) {
            atomicAdd(&g_sum[co], (double)rs1);
            atomicAdd(&g_sumsq[co], (double)rs2);
        }
    }
}

// ---------------- BN finalize ----------------
__global__ void bn_finalize(const float* __restrict__ gg, const float* __restrict__ gb) {
    int c = threadIdx.x;
    if (c < 10) {
        double cnt = (double)BATCH * 62.0 * 62.0;
        double mean = g_sum[c] / cnt;
        double var = g_sumsq[c] / cnt - mean * mean;
        float istd = (float)(1.0 / sqrt(var + 1e-5));
        float a = gg[c] * istd;
        g_bnA[c] = a;
        g_bnB[c] = gb[c] - (float)mean * a;
    }
}

// ---------------- BN + ReLU + maxpool2 ----------------
__global__ __launch_bounds__(256) void bnpool_kernel() {
    size_t total = (size_t)BATCH * C1O * P1 * P1;
    size_t stride = (size_t)gridDim.x * blockDim.x;
    for (size_t idx = (size_t)blockIdx.x * blockDim.x + threadIdx.x; idx < total; idx += stride) {
        int j = (int)(idx % 31); size_t t = idx / 31;
        int i = (int)(t % 31); t /= 31;
        int c = (int)(t % 10); int n = (int)(t / 10);
        size_t base = (((size_t)n * 10 + c) * 62 + 2 * i) * 62 + 2 * j;
        float a = g_bnA[c], bb = g_bnB[c];
        float v0 = fmaf(a, g_c1[base], bb);
        float v1 = fmaf(a, g_c1[base + 1], bb);
        float v2 = fmaf(a, g_c1[base + 62], bb);
        float v3 = fmaf(a, g_c1[base + 63], bb);
        float m = fmaxf(fmaxf(v0, v1), fmaxf(v2, v3));
        g_p1[idx] = fmaxf(m, 0.f);
    }
}

// ---------------- conv2 (10->20, 5x5, pad1) + ReLU + maxpool2 -> feat ----------------
__global__ __launch_bounds__(512) void conv2_kernel(const float* __restrict__ w,
                                                    const float* __restrict__ b) {
    extern __shared__ float sm[];
    float* pin = sm;            // [10][33][38] = 12540
    float* ws  = sm + 12540;    // 5000
    float* bs  = ws + 5000;     // 20
    const int n = blockIdx.x, tid = threadIdx.x;

    for (int i = tid; i < 12540; i += 512) pin[i] = 0.f;
    for (int i = tid; i < 5000; i += 512) ws[i] = w[i];
    if (tid < 20) bs[tid] = b[tid];
    __syncthreads();

    const float* pn = g_p1 + (size_t)n * 10 * 31 * 31;
    for (int i = tid; i < 10 * 31 * 31; i += 512) {
        int c = i / 961, r = (i / 31) % 31, cc = i % 31;
        pin[(c * 33 + r + 1) * 38 + cc + 1] = pn[i];
    }
    __syncthreads();

    for (int g = tid; g < 20 * 14 * 4; g += 512) {
        int co = g / 56; int rem = g % 56;
        int i2 = rem >> 2; int jg = rem & 3;
        int c0 = jg * 8;
        float a0[8], a1[8];
#pragma unroll
        for (int j = 0; j < 8; j++) { a0[j] = bs[co]; a1[j] = bs[co]; }
#pragma unroll
        for (int ci = 0; ci < 10; ci++) {
            const float* wb = &ws[(co * 10 + ci) * 25];
#pragma unroll
            for (int ry = 0; ry < 6; ry++) {
                const float* row = &pin[(ci * 33 + 2 * i2 + ry) * 38 + c0];
                float rr[12];
#pragma unroll
                for (int t = 0; t < 12; t++) rr[t] = row[t];
                if (ry < 5) {
                    const float* wr = wb + ry * 5;
#pragma unroll
                    for (int kx = 0; kx < 5; kx++) {
                        float wv = wr[kx];
#pragma unroll
                        for (int j = 0; j < 8; j++) a0[j] = fmaf(rr[j + kx], wv, a0[j]);
                    }
                }
                if (ry >= 1) {
                    const float* wr = wb + (ry - 1) * 5;
#pragma unroll
                    for (int kx = 0; kx < 5; kx++) {
                        float wv = wr[kx];
#pragma unroll
                        for (int j = 0; j < 8; j++) a1[j] = fmaf(rr[j + kx], wv, a1[j]);
                    }
                }
            }
        }
        size_t ob = (size_t)n * FEAT + co * 196 + i2 * 14;
#pragma unroll
        for (int j2 = 0; j2 < 4; j2++) {
            int j = jg * 4 + j2;
            if (j < 14) {
                float m = fmaxf(fmaxf(a0[2 * j2], a0[2 * j2 + 1]),
                                fmaxf(a1[2 * j2], a1[2 * j2 + 1]));
                g_feat[ob + j] = fmaxf(m, 0.f);
            }
        }
    }
}

// ---------------- gate layer 2 + top-2 + list build ----------------
__global__ __launch_bounds__(256) void gate2_kernel(const float* __restrict__ w2,
                                                    const float* __restrict__ b2) {
    __shared__ float ws[NE * GH], bs[NE];
    int tid = threadIdx.x;
    for (int i = tid; i < NE * GH; i += 256) ws[i] = w2[i];
    if (tid < NE) bs[tid] = b2[tid];
    __syncthreads();

    int bsmp = blockIdx.x * 256 + tid;
    if (bsmp >= BATCH) return;
    float h[GH];
    const float* row = g_gh + (size_t)bsmp * GH;
#pragma unroll
    for (int i = 0; i < GH; i++) h[i] = row[i];

    float lg[NE];
#pragma unroll
    for (int e = 0; e < NE; e++) {
        float s = bs[e];
        const float* wr = &ws[e * GH];
#pragma unroll
        for (int i = 0; i < GH; i++) s = fmaf(h[i], wr[i], s);
        lg[e] = s;
    }
    int i0 = 0;
#pragma unroll
    for (int e = 1; e < NE; e++) if (lg[e] > lg[i0]) i0 = e;
    int i1 = (i0 == 0) ? 1 : 0;
#pragma unroll
    for (int e = 0; e < NE; e++) if (e != i0 && lg[e] > lg[i1]) i1 = e;
    float w0 = 1.f / (1.f + expf(lg[i1] - lg[i0]));
    float w1 = 1.f - w0;

    int p0 = atomicAdd(&g_cnt[i0], 1);
    int item0 = bsmp * 2;
    g_list[i0 * BATCH + p0] = item0;
    g_gatew[item0] = w0;
    int p1 = atomicAdd(&g_cnt[i1], 1);
    int item1 = bsmp * 2 + 1;
    g_list[i1 * BATCH + p1] = item1;
    g_gatew[item1] = w1;
}

// ---------------- NT GEMM: C[m,n] = sum_k A[m,k]*W[n,k], 64x64 tile, 4x4/thread ----
// MODE 0: gate fc1 (dense g_feat -> g_gh, relu)
// MODE 1: expert fc1 (gather g_feat -> g_h1, relu)
// MODE 2: expert fc2 (gather g_h1 -> g_h2, relu)
// MODE 3: expert fc3 (gather g_h2 -> atomicAdd gate*(acc+bias) into d_out)
template <int MODE>
__global__ __launch_bounds__(256) void sgemm_nt(const float* __restrict__ W0,
                                                const float* __restrict__ bias0,
                                                float* __restrict__ C0,
                                                int N, int K) {
    const int e = blockIdx.z;
    const int m0 = blockIdx.x * 64, n0 = blockIdx.y * 64;
    const int Me = (MODE == 0) ? BATCH : g_cnt[e];
    if (m0 >= Me) return;
    const int* list = g_list + e * BATCH;
    const float* W = W0 + (size_t)e * N * K;
    const float* bias = bias0 + (size_t)e * N;

    __shared__ __align__(16) float As[16][68], Ws[16][68];
    const int tid = threadIdx.x;
    const int lm = tid >> 2, lq = tid & 3;

    const float* arow = nullptr;
    bool mv = (m0 + lm) < Me;
    if (mv) {
        if (MODE == 0) arow = g_feat + (size_t)(m0 + lm) * K;
        else {
            int item = list[m0 + lm];
            arow = (MODE == 1) ? (g_feat + (size_t)(item >> 1) * K)
                 : (MODE == 2) ? (g_h1 + (size_t)item * K)
                               : (g_h2 + (size_t)item * K);
        }
    }
    bool nv = (n0 + lm) < N;
    const float* wrow = nv ? (W + (size_t)(n0 + lm) * K) : nullptr;

    const int tx = tid & 15, ty = tid >> 4;
    float acc[4][4];
#pragma unroll
    for (int i = 0; i < 4; i++)
#pragma unroll
        for (int j = 0; j < 4; j++) acc[i][j] = 0.f;

    const int ktn = K >> 4;
    for (int kt = 0; kt < ktn; kt++) {
        int k0 = (kt << 4) + (lq << 2);
        float4 av = mv ? *(const float4*)(arow + k0) : make_float4(0, 0, 0, 0);
        float4 wv = nv ? *(const float4*)(wrow + k0) : make_float4(0, 0, 0, 0);
        __syncthreads();
        As[lq * 4 + 0][lm] = av.x; As[lq * 4 + 1][lm] = av.y;
        As[lq * 4 + 2][lm] = av.z; As[lq * 4 + 3][lm] = av.w;
        Ws[lq * 4 + 0][lm] = wv.x; Ws[lq * 4 + 1][lm] = wv.y;
        Ws[lq * 4 + 2][lm] = wv.z; Ws[lq * 4 + 3][lm] = wv.w;
        __syncthreads();
#pragma unroll
        for (int kk = 0; kk < 16; kk++) {
            float4 a4 = *(const float4*)&As[kk][ty << 2];
            float4 w4 = *(const float4*)&Ws[kk][tx << 2];
            float aa[4] = {a4.x, a4.y, a4.z, a4.w};
            float ww[4] = {w4.x, w4.y, w4.z, w4.w};
#pragma unroll
            for (int i = 0; i < 4; i++)
#pragma unroll
                for (int j = 0; j < 4; j++) acc[i][j] = fmaf(aa[i], ww[j], acc[i][j]);
        }
    }

#pragma unroll
    for (int i = 0; i < 4; i++) {
        int m = m0 + (ty << 2) + i;
        if (m >= Me) continue;
        int item = 0;
        if (MODE != 0) item = list[m];
#pragma unroll
        for (int j = 0; j < 4; j++) {
            int nn = n0 + (tx << 2) + j;
            if (nn >= N) continue;
            float v = acc[i][j] + bias[nn];
            if (MODE == 0)      g_gh[(size_t)m * GH + nn] = fmaxf(v, 0.f);
            else if (MODE == 1) g_h1[(size_t)item * HID + nn] = fmaxf(v, 0.f);
            else if (MODE == 2) g_h2[(size_t)item * HID2 + nn] = fmaxf(v, 0.f);
            else atomicAdd(&C0[(size_t)(item >> 1) * NOUT + nn], g_gatew[item] * v);
        }
    }
}

// ---------------- final: out = log_softmax(|out|) per row ----------------
__global__ __launch_bounds__(256) void logsoftmax_kernel(float* __restrict__ out) {
    __shared__ float red[32];
    int b = blockIdx.x, tid = threadIdx.x;
    float* row = out + (size_t)b * NOUT;

    float m = -1e30f;
    for (int i = tid; i < NOUT; i += 256) m = fmaxf(m, fabsf(row[i]));
#pragma unroll
    for (int off = 16; off > 0; off >>= 1) m = fmaxf(m, __shfl_xor_sync(0xffffffffu, m, off));
    if ((tid & 31) == 0) red[tid >> 5] = m;
    __syncthreads();
    if (tid < 32) {
        float v = (tid < 8) ? red[tid] : -1e30f;
#pragma unroll
        for (int off = 4; off > 0; off >>= 1) v = fmaxf(v, __shfl_xor_sync(0xffffffffu, v, off));
        if (tid == 0) red[0] = v;
    }
    __syncthreads();
    m = red[0];
    __syncthreads();

    float s = 0.f;
    for (int i = tid; i < NOUT; i += 256) s += expf(fabsf(row[i]) - m);
#pragma unroll
    for (int off = 16; off > 0; off >>= 1) s += __shfl_xor_sync(0xffffffffu, s, off);
    if ((tid & 31) == 0) red[tid >> 5] = s;
    __syncthreads();
    if (tid < 32) {
        float v = (tid < 8) ? red[tid] : 0.f;
#pragma unroll
        for (int off = 4; off > 0; off >>= 1) v += __shfl_xor_sync(0xffffffffu, v, off);
        if (tid == 0) red[0] = v;
    }
    __syncthreads();
    float lse = m + logf(red[0]);
    for (int i = tid; i < NOUT; i += 256) row[i] = fabsf(row[i]) - lse;
}

// ---------------- launch ----------------
extern "C" void kernel_launch(void* const* d_in, const int* in_sizes, int n_in,
                              void* d_out, int out_size) {
    const float* x       = (const float*)d_in[0];
    const float* conv1_w = (const float*)d_in[1];
    const float* conv1_b = (const float*)d_in[2];
    const float* bn_g    = (const float*)d_in[3];
    const float* bn_b    = (const float*)d_in[4];
    const float* conv2_w = (const float*)d_in[5];
    const float* conv2_b = (const float*)d_in[6];
    const float* gate_w1 = (const float*)d_in[7];
    const float* gate_b1 = (const float*)d_in[8];
    const float* gate_w2 = (const float*)d_in[9];
    const float* gate_b2 = (const float*)d_in[10];
    const float* ew1     = (const float*)d_in[11];
    const float* eb1     = (const float*)d_in[12];
    const float* ew2     = (const float*)d_in[13];
    const float* eb2     = (const float*)d_in[14];
    const float* ew3     = (const float*)d_in[15];
    const float* eb3     = (const float*)d_in[16];
    float* out = (float*)d_out;

    static bool attr_done = false;
    if (!attr_done) {
        cudaFuncSetAttribute(conv1_kernel, cudaFuncAttributeMaxDynamicSharedMemorySize, 57344);
        cudaFuncSetAttribute(conv2_kernel, cudaFuncAttributeMaxDynamicSharedMemorySize, 71680);
        attr_done = true;
    }

    init_kernel<<<1024, 256>>>(out);
    conv1_kernel<<<BATCH, 256, 56896>>>(x, conv1_w, conv1_b);
    bn_finalize<<<1, 32>>>(bn_g, bn_b);
    bnpool_kernel<<<4096, 256>>>();
    conv2_kernel<<<BATCH, 512, 70240>>>(conv2_w, conv2_b);
    sgemm_nt<0><<<dim3(64, 1, 1), 256>>>(gate_w1, gate_b1, nullptr, GH, FEAT);
    gate2_kernel<<<16, 256>>>(gate_w2, gate_b2);
    sgemm_nt<1><<<dim3(64, 2, NE), 256>>>(ew1, eb1, nullptr, HID, FEAT);
    sgemm_nt<2><<<dim3(64, 1, NE), 256>>>(ew2, eb2, nullptr, HID2, HID);
    sgemm_nt<3><<<dim3(64, 16, NE), 256>>>(ew3, eb3, out, NOUT, HID2);
    logsoftmax_kernel<<<BATCH, 256>>>(out);
}